// round 2
// baseline (speedup 1.0000x reference)
#include <cuda_runtime.h>
#include <cstdint>

// Problem constants
#define NROWS 10000
#define KDIM  10000
#define F     20      // hidden width
#define D     128     // in/out width
#define BK    200     // k-chunk for the big GEMM (10000 = 50*200)
#define KSTEPS (BK/8) // 25 mma k-steps per chunk
#define NSTRIPS (NROWS/16)  // 625 (exact)
#define TS_PAD 32     // pad so n-tile over-read (cols 20..23 on last k-row) stays in bounds

// Scratch (no allocations allowed): two ping-pong N x 20 buffers.
__device__ float g_bufT[NROWS * F];
__device__ float g_bufH[NROWS * F];

__device__ __forceinline__ uint32_t f2tf(float f) {
    uint32_t u;
    asm("cvt.rna.tf32.f32 %0, %1;" : "=r"(u) : "f"(f));
    return u;
}

// ---------------------------------------------------------------------------
// Big GEMM: out[N,20] = adj[N,N] @ T[N,20]  (+bias, relu if DO_EPI)
// Per-warp 16-row strip, 3 n-tiles of 8 (cols 20..23 padded/discarded).
// k-within-8 permuted (frag col c <-> global k = 2*(c&3) + (c>>2)) so:
//   - A fragment loads are contiguous float2 per lane (LDG.64)
//   - B smem reads at natural stride 20 are bank-conflict-free
// ---------------------------------------------------------------------------
template <int DO_EPI>
__global__ void __launch_bounds__(64)
spmm_kernel(const float* __restrict__ adj,
            const float* __restrict__ T,
            const float* __restrict__ bias,
            float* __restrict__ out)
{
    __shared__ uint32_t Ts[BK * F + TS_PAD];  // tf32 bits, natural stride 20

    const int tid  = threadIdx.x;
    const int warp = tid >> 5;
    const int lane = tid & 31;
    const int gid  = lane >> 2;   // 0..7  (row-in-group)
    const int tig  = lane & 3;    // 0..3  (k selector)

    // zero the pad once (read-only garbage region for n-tile overhang)
    if (tid < TS_PAD) Ts[BK * F + tid] = 0;

    const int strip  = blockIdx.x * 2 + warp;
    const bool active = (strip < NSTRIPS);
    const int m0 = strip * 16;

    const float* a_row0 = adj + (size_t)(m0 + gid) * KDIM;
    const float* a_row1 = a_row0 + (size_t)8 * KDIM;

    float acc[3][4];
#pragma unroll
    for (int t = 0; t < 3; t++)
#pragma unroll
        for (int j = 0; j < 4; j++) acc[t][j] = 0.0f;

    for (int ch = 0; ch < KDIM / BK; ++ch) {
        __syncthreads();   // previous chunk's LDS done before overwrite
        {
            // stage B chunk (BK*20 = 4000 floats, contiguous) as tf32
            const float4* src = (const float4*)(T + (size_t)ch * BK * F);
            uint4* dst = (uint4*)Ts;
            for (int i = tid; i < (BK * F) / 4; i += 64) {
                float4 v = src[i];
                uint4 u;
                u.x = f2tf(v.x); u.y = f2tf(v.y);
                u.z = f2tf(v.z); u.w = f2tf(v.w);
                dst[i] = u;
            }
        }
        __syncthreads();

        if (active) {
            const int kbase = ch * BK;
#pragma unroll 5
            for (int ks = 0; ks < KSTEPS; ++ks) {
                const int k2 = kbase + ks * 8 + 2 * tig;   // contiguous pair
                float2 va = *(const float2*)(a_row0 + k2);
                float2 vb = *(const float2*)(a_row1 + k2);
                uint32_t a0 = f2tf(va.x);   // frag col tig   (global 2*tig)
                uint32_t a2 = f2tf(va.y);   // frag col tig+4 (global 2*tig+1)
                uint32_t a1 = f2tf(vb.x);
                uint32_t a3 = f2tf(vb.y);

                const int bs0 = (ks * 8 + 2 * tig)     * F;  // frag row tig
                const int bs1 = (ks * 8 + 2 * tig + 1) * F;  // frag row tig+4
#pragma unroll
                for (int t = 0; t < 3; t++) {
                    uint32_t b0 = Ts[bs0 + 8 * t + gid];
                    uint32_t b1 = Ts[bs1 + 8 * t + gid];
                    asm volatile(
                        "mma.sync.aligned.m16n8k8.row.col.f32.tf32.tf32.f32 "
                        "{%0,%1,%2,%3},{%4,%5,%6,%7},{%8,%9},{%0,%1,%2,%3};"
                        : "+f"(acc[t][0]), "+f"(acc[t][1]),
                          "+f"(acc[t][2]), "+f"(acc[t][3])
                        : "r"(a0), "r"(a1), "r"(a2), "r"(a3),
                          "r"(b0), "r"(b1));
                }
            }
        }
    }

    if (active) {
#pragma unroll
        for (int t = 0; t < 3; t++) {
            const int c = 8 * t + 2 * tig;   // col pairs never straddle 20
            if (c < F) {
                const int r0 = m0 + gid;
                const int r1 = r0 + 8;
                float2 v0, v1;
                if (DO_EPI) {
                    const float bc0 = bias[c], bc1 = bias[c + 1];
                    v0 = make_float2(fmaxf(acc[t][0] + bc0, 0.f),
                                     fmaxf(acc[t][1] + bc1, 0.f));
                    v1 = make_float2(fmaxf(acc[t][2] + bc0, 0.f),
                                     fmaxf(acc[t][3] + bc1, 0.f));
                } else {
                    v0 = make_float2(acc[t][0], acc[t][1]);
                    v1 = make_float2(acc[t][2], acc[t][3]);
                }
                *(float2*)(out + (size_t)r0 * F + c) = v0;
                *(float2*)(out + (size_t)r1 * F + c) = v1;
            }
        }
    }
}

// ---------------------------------------------------------------------------
// Small GEMM: T[N,20] = Hin[N,KK] @ W[KK,20].  Warp per row, lane = out col.
// ---------------------------------------------------------------------------
template <int KK>
__global__ void __launch_bounds__(256)
xw_kernel(const float* __restrict__ Hin, const float* __restrict__ W,
          float* __restrict__ T)
{
    __shared__ float Ws[KK * F];
    const int tid = threadIdx.x;
    for (int i = tid; i < KK * F; i += 256) Ws[i] = W[i];
    __syncthreads();

    const int warp = tid >> 5;
    const int lane = tid & 31;
    const int row  = blockIdx.x * 8 + warp;   // grid*8 == NROWS exactly

    const float* h = Hin + (size_t)row * KK;
    if (lane < F) {
        float a0 = 0.f, a1 = 0.f, a2 = 0.f, a3 = 0.f;
#pragma unroll 4
        for (int k = 0; k < KK; k += 4) {
            a0 += h[k + 0] * Ws[(k + 0) * F + lane];
            a1 += h[k + 1] * Ws[(k + 1) * F + lane];
            a2 += h[k + 2] * Ws[(k + 2) * F + lane];
            a3 += h[k + 3] * Ws[(k + 3) * F + lane];
        }
        T[(size_t)row * F + lane] = (a0 + a1) + (a2 + a3);
    }
}

// ---------------------------------------------------------------------------
// Final: out = relu( relu(P @ W3 + b3) + x )
// ---------------------------------------------------------------------------
__global__ void __launch_bounds__(256)
final_kernel(const float* __restrict__ P, const float* __restrict__ W3,
             const float* __restrict__ b3, const float* __restrict__ x,
             float* __restrict__ out)
{
    __shared__ float Ws[F * D];    // 20 x 128
    const int tid = threadIdx.x;
    for (int i = tid; i < F * D; i += 256) Ws[i] = W3[i];
    __syncthreads();

    const int row = blockIdx.x * 2 + (tid >> 7);
    const int col = tid & 127;
    const float* p = P + (size_t)row * F;

    float acc = b3[col];
#pragma unroll
    for (int k = 0; k < F; k++) acc += p[k] * Ws[k * D + col];

    const float h = fmaxf(acc, 0.f);
    const size_t o = (size_t)row * D + col;
    out[o] = fmaxf(h + x[o], 0.f);
}

// ---------------------------------------------------------------------------
extern "C" void kernel_launch(void* const* d_in, const int* in_sizes, int n_in,
                              void* d_out, int out_size)
{
    const float* x   = (const float*)d_in[0];
    const float* adj = (const float*)d_in[1];
    const float* W1  = (const float*)d_in[2];
    const float* b1  = (const float*)d_in[3];
    const float* W2  = (const float*)d_in[4];
    const float* b2  = (const float*)d_in[5];
    const float* W3  = (const float*)d_in[6];
    const float* b3  = (const float*)d_in[7];
    float* out = (float*)d_out;

    float *T, *H;
    cudaGetSymbolAddress((void**)&T, g_bufT);
    cudaGetSymbolAddress((void**)&H, g_bufH);

    const int SPMM_GRID = (NSTRIPS + 1) / 2;   // 313 blocks x 64 thr

    // T1 = x @ W1
    xw_kernel<D><<<NROWS / 8, 256>>>(x, W1, T);
    // H1 = relu(adj @ T1 + b1)
    spmm_kernel<1><<<SPMM_GRID, 64>>>(adj, T, b1, H);
    // T2 = H1 @ W2
    xw_kernel<F><<<NROWS / 8, 256>>>(H, W2, T);
    // H2 = relu(adj @ T2 + b2)
    spmm_kernel<1><<<SPMM_GRID, 64>>>(adj, T, b2, H);
    // P3 = adj @ H2   (raw, bias/relu folded into final kernel)
    spmm_kernel<0><<<SPMM_GRID, 64>>>(adj, H, b1 /*unused*/, T);
    // out = relu(relu(P3 @ W3 + b3) + x)
    final_kernel<<<NROWS / 2, 256>>>(T, W3, b3, x, out);
}

// round 3
// speedup vs baseline: 2.7704x; 2.7704x over previous
#include <cuda_runtime.h>
#include <cstdint>

// Problem constants
#define NROWS 10000
#define KDIM  10000
#define F     20      // hidden width
#define D     128     // in/out width
#define BK    200     // k-chunk for the big GEMM
#define KSTEPS (BK/8) // 25 mma k-steps per chunk
#define NSTRIPS ((NROWS + 15) / 16)   // 625 (exact)
#define TS_PAD 32     // pad so n-tile over-read (cols 20..23 on last k-row) stays in bounds

// K-split for occupancy: 5 slabs of 2000 columns each
#define SPLIT  5
#define SLAB   (KDIM / SPLIT)   // 2000
#define CHUNKS (SLAB / BK)      // 10
#define STRIPS_PER_BLK 8
#define NSTRIP_GROUPS ((NSTRIPS + STRIPS_PER_BLK - 1) / STRIPS_PER_BLK)  // 79

// Scratch (no allocations allowed)
__device__ float g_bufT[NROWS * F];
__device__ float g_bufH[NROWS * F];
__device__ float g_part[SPLIT * NROWS * F];   // 4 MB partials

__device__ __forceinline__ uint32_t f2tf(float f) {
    uint32_t u;
    asm("cvt.rna.tf32.f32 %0, %1;" : "=r"(u) : "f"(f));
    return u;
}

// ---------------------------------------------------------------------------
// Big GEMM partial: part[slab][N,20] = adj[:, slab] @ T[slab, 20]
// Per-warp 16-row strip over ONE k-slab. 8 warps/block share B staging.
// k-within-8 permuted (frag col c <-> global k = 2*(c&3) + (c>>2)) so A loads
// are contiguous float2 per lane and B smem reads are conflict-free.
// ---------------------------------------------------------------------------
__global__ void __launch_bounds__(256)
spmm_part_kernel(const float* __restrict__ adj,
                 const float* __restrict__ T,
                 float* __restrict__ part)
{
    __shared__ uint32_t Ts[BK * F + TS_PAD];  // tf32 bits, natural stride 20

    const int tid  = threadIdx.x;
    const int warp = tid >> 5;
    const int lane = tid & 31;
    const int gid  = lane >> 2;   // 0..7  (row-in-group)
    const int tig  = lane & 3;    // 0..3  (k selector)

    if (tid < TS_PAD) Ts[BK * F + tid] = 0;   // benign pad for n-tile overhang

    const int strip  = blockIdx.x * STRIPS_PER_BLK + warp;
    const bool active = (strip < NSTRIPS);
    const int m0   = strip * 16;
    const int slab = blockIdx.y;

    // A pointers: this warp's rows, offset to this slab's column window
    const float* a_row0 = adj + (size_t)(active ? (m0 + gid) : 0) * KDIM
                              + (size_t)slab * SLAB;
    const float* a_row1 = a_row0 + (size_t)8 * KDIM;

    float acc[3][4];
#pragma unroll
    for (int t = 0; t < 3; t++)
#pragma unroll
        for (int j = 0; j < 4; j++) acc[t][j] = 0.0f;

    for (int ch = 0; ch < CHUNKS; ++ch) {
        __syncthreads();   // previous chunk's LDS done before overwrite
        {
            // stage B chunk (BK*20 = 4000 floats, contiguous) as tf32
            const float4* src =
                (const float4*)(T + ((size_t)slab * SLAB + (size_t)ch * BK) * F);
            uint4* dst = (uint4*)Ts;
#pragma unroll
            for (int it = 0; it < (BK * F) / 4 / 256 + 1; ++it) {
                int i = it * 256 + tid;
                if (i < (BK * F) / 4) {
                    float4 v = src[i];
                    uint4 u;
                    u.x = f2tf(v.x); u.y = f2tf(v.y);
                    u.z = f2tf(v.z); u.w = f2tf(v.w);
                    dst[i] = u;
                }
            }
        }
        __syncthreads();

        if (active) {
            const int kbase = ch * BK;
            // software pipeline: prefetch next kstep's A while MMA-ing current
            float2 va = *(const float2*)(a_row0 + kbase + 2 * tig);
            float2 vb = *(const float2*)(a_row1 + kbase + 2 * tig);
#pragma unroll
            for (int ks = 0; ks < KSTEPS; ++ks) {
                float2 na, nb;
                if (ks + 1 < KSTEPS) {
                    const int kn = kbase + (ks + 1) * 8 + 2 * tig;
                    na = *(const float2*)(a_row0 + kn);
                    nb = *(const float2*)(a_row1 + kn);
                }
                uint32_t a0 = f2tf(va.x);   // frag col tig   (global 2*tig)
                uint32_t a2 = f2tf(va.y);   // frag col tig+4 (global 2*tig+1)
                uint32_t a1 = f2tf(vb.x);
                uint32_t a3 = f2tf(vb.y);

                const int bs0 = (ks * 8 + 2 * tig)     * F;  // frag row tig
                const int bs1 = (ks * 8 + 2 * tig + 1) * F;  // frag row tig+4
#pragma unroll
                for (int t = 0; t < 3; t++) {
                    uint32_t b0 = Ts[bs0 + 8 * t + gid];
                    uint32_t b1 = Ts[bs1 + 8 * t + gid];
                    asm volatile(
                        "mma.sync.aligned.m16n8k8.row.col.f32.tf32.tf32.f32 "
                        "{%0,%1,%2,%3},{%4,%5,%6,%7},{%8,%9},{%0,%1,%2,%3};"
                        : "+f"(acc[t][0]), "+f"(acc[t][1]),
                          "+f"(acc[t][2]), "+f"(acc[t][3])
                        : "r"(a0), "r"(a1), "r"(a2), "r"(a3),
                          "r"(b0), "r"(b1));
                }
                va = na; vb = nb;
            }
        }
    }

    if (active) {
        float* po = part + (size_t)slab * NROWS * F;
#pragma unroll
        for (int t = 0; t < 3; t++) {
            const int c = 8 * t + 2 * tig;   // col pairs never straddle 20
            if (c < F) {
                const int r0 = m0 + gid;
                const int r1 = r0 + 8;
                *(float2*)(po + (size_t)r0 * F + c) =
                    make_float2(acc[t][0], acc[t][1]);
                *(float2*)(po + (size_t)r1 * F + c) =
                    make_float2(acc[t][2], acc[t][3]);
            }
        }
    }
}

// ---------------------------------------------------------------------------
// Reduce partials: out[i] = (relu?) ( sum_s part[s][i] + bias[i%20] )
// ---------------------------------------------------------------------------
template <int DO_RELU>
__global__ void __launch_bounds__(256)
reduce_kernel(const float* __restrict__ part, const float* __restrict__ bias,
              float* __restrict__ out)
{
    const int i = blockIdx.x * 256 + threadIdx.x;
    if (i < NROWS * F) {
        float s = 0.f;
#pragma unroll
        for (int sl = 0; sl < SPLIT; sl++)
            s += part[(size_t)sl * NROWS * F + i];
        if (DO_RELU) s = fmaxf(s + bias[i % F], 0.f);
        out[i] = s;
    }
}

// ---------------------------------------------------------------------------
// Small GEMM: T[N,20] = Hin[N,KK] @ W[KK,20].  Warp per row, lane = out col.
// ---------------------------------------------------------------------------
template <int KK>
__global__ void __launch_bounds__(256)
xw_kernel(const float* __restrict__ Hin, const float* __restrict__ W,
          float* __restrict__ T)
{
    __shared__ float Ws[KK * F];
    const int tid = threadIdx.x;
    for (int i = tid; i < KK * F; i += 256) Ws[i] = W[i];
    __syncthreads();

    const int warp = tid >> 5;
    const int lane = tid & 31;
    const int row  = blockIdx.x * 8 + warp;   // grid*8 == NROWS exactly

    const float* h = Hin + (size_t)row * KK;
    if (lane < F) {
        float a0 = 0.f, a1 = 0.f, a2 = 0.f, a3 = 0.f;
#pragma unroll 4
        for (int k = 0; k < KK; k += 4) {
            a0 += h[k + 0] * Ws[(k + 0) * F + lane];
            a1 += h[k + 1] * Ws[(k + 1) * F + lane];
            a2 += h[k + 2] * Ws[(k + 2) * F + lane];
            a3 += h[k + 3] * Ws[(k + 3) * F + lane];
        }
        T[(size_t)row * F + lane] = (a0 + a1) + (a2 + a3);
    }
}

// ---------------------------------------------------------------------------
// Final: out = relu( relu(P @ W3 + b3) + x )
// ---------------------------------------------------------------------------
__global__ void __launch_bounds__(256)
final_kernel(const float* __restrict__ P, const float* __restrict__ W3,
             const float* __restrict__ b3, const float* __restrict__ x,
             float* __restrict__ out)
{
    __shared__ float Ws[F * D];    // 20 x 128
    const int tid = threadIdx.x;
    for (int i = tid; i < F * D; i += 256) Ws[i] = W3[i];
    __syncthreads();

    const int row = blockIdx.x * 2 + (tid >> 7);
    const int col = tid & 127;
    const float* p = P + (size_t)row * F;

    float acc = b3[col];
#pragma unroll
    for (int k = 0; k < F; k++) acc += p[k] * Ws[k * D + col];

    const float h = fmaxf(acc, 0.f);
    const size_t o = (size_t)row * D + col;
    out[o] = fmaxf(h + x[o], 0.f);
}

// ---------------------------------------------------------------------------
extern "C" void kernel_launch(void* const* d_in, const int* in_sizes, int n_in,
                              void* d_out, int out_size)
{
    const float* x   = (const float*)d_in[0];
    const float* adj = (const float*)d_in[1];
    const float* W1  = (const float*)d_in[2];
    const float* b1  = (const float*)d_in[3];
    const float* W2  = (const float*)d_in[4];
    const float* b2  = (const float*)d_in[5];
    const float* W3  = (const float*)d_in[6];
    const float* b3  = (const float*)d_in[7];
    float* out = (float*)d_out;

    float *T, *H, *P;
    cudaGetSymbolAddress((void**)&T, g_bufT);
    cudaGetSymbolAddress((void**)&H, g_bufH);
    cudaGetSymbolAddress((void**)&P, g_part);

    const dim3 SPMM_GRID(NSTRIP_GROUPS, SPLIT);          // 79 x 5 blocks, 256 thr
    const int  RED_GRID = (NROWS * F + 255) / 256;       // 782

    // T1 = x @ W1
    xw_kernel<D><<<NROWS / 8, 256>>>(x, W1, T);
    // H1 = relu(adj @ T1 + b1)
    spmm_part_kernel<<<SPMM_GRID, 256>>>(adj, T, P);
    reduce_kernel<1><<<RED_GRID, 256>>>(P, b1, H);
    // T2 = H1 @ W2
    xw_kernel<F><<<NROWS / 8, 256>>>(H, W2, T);
    // H2 = relu(adj @ T2 + b2)
    spmm_part_kernel<<<SPMM_GRID, 256>>>(adj, T, P);
    reduce_kernel<1><<<RED_GRID, 256>>>(P, b2, H);
    // P3 = adj @ H2   (raw, bias/relu folded into final kernel)
    spmm_part_kernel<<<SPMM_GRID, 256>>>(adj, H, P);
    reduce_kernel<0><<<RED_GRID, 256>>>(P, b3 /*unused*/, T);
    // out = relu(relu(P3 @ W3 + b3) + x)
    final_kernel<<<NROWS / 2, 256>>>(T, W3, b3, x, out);
}